// round 12
// baseline (speedup 1.0000x reference)
#include <cuda_runtime.h>
#include <cuda_fp16.h>
#include <stdint.h>

#define THREADS 256
#define ROWSB   128

// ---- shared memory float offsets ----
#define PAR_BIN  0
#define PAR_G1   64
#define PAR_BE1  128
#define PAR_B1   192      // (unused slot, kept for layout stability)
#define PAR_B2   256
#define PAR_G2   320
#define PAR_BE2  384
#define PAR_BOUT 448
#define PAR_WOUT 464                     // 640 floats -> ends 1104
#define PAR_B1H  1104                    // 32 packed fp16x2 words -> ends 1136
#define OFF_XS0  1152                    // x chunk buf0: 128 rows * 36 words
#define OFF_XS1  (OFF_XS0 + 4608)
#define OFF_WA   (OFF_XS1 + 4608)        // W1 frags / W_in even chunks: 1024 uint2
#define OFF_WB   (OFF_WA + 2048)         // W2 frags / W_in odd chunks
#define SMEM_FLOATS (OFF_WB + 2048)      // 14464 floats = 57856 B

__device__ __forceinline__ uint32_t packh2(float v0, float v1) {
    __half2 t = __floats2half2_rn(v0, v1);
    return *reinterpret_cast<uint32_t*>(&t);
}
__device__ __forceinline__ uint32_t hadd2(uint32_t a, uint32_t b) {
    uint32_t r; asm("add.rn.f16x2 %0, %1, %2;" : "=r"(r) : "r"(a), "r"(b)); return r;
}
__device__ __forceinline__ void mma16816(float* c, const uint32_t* a, uint32_t b0, uint32_t b1) {
    asm("mma.sync.aligned.m16n8k16.row.col.f32.f16.f16.f32 "
        "{%0,%1,%2,%3}, {%4,%5,%6,%7}, {%8,%9}, {%0,%1,%2,%3};\n"
        : "+f"(c[0]), "+f"(c[1]), "+f"(c[2]), "+f"(c[3])
        : "r"(a[0]), "r"(a[1]), "r"(a[2]), "r"(a[3]), "r"(b0), "r"(b1));
}
// packed fp16x2 tanh (hardware approx)
__device__ __forceinline__ uint32_t tanh2(uint32_t x) {
    uint32_t r; asm("tanh.approx.f16x2 %0, %1;" : "=r"(r) : "r"(x)); return r;
}
// accurate tanh for GroupNorm1 output (feeds fp32 h state)
__device__ __forceinline__ float tanhfast(float x) {
    float e;
    asm("ex2.approx.f32 %0, %1;" : "=f"(e) : "f"(x * 2.8853900817779268f));
    float d = e + 1.0f, i;
    asm("rcp.approx.f32 %0, %1;" : "=f"(i) : "f"(d));
    return fmaf(-2.0f, i, 1.0f);
}

// ODE-loop GEMM: C[16x64/warp] = A @ W, fp16; A pre-packed as av[16]
__device__ __forceinline__ void gemm64(const uint32_t av[16],
                                       const uint2* __restrict__ wQ,
                                       float c[8][4], int q, int r) {
#pragma unroll
    for (int j = 0; j < 8; ++j) { c[j][0]=0.f; c[j][1]=0.f; c[j][2]=0.f; c[j][3]=0.f; }
#pragma unroll
    for (int t = 0; t < 4; ++t) {
        const uint32_t* a = av + 4*t;
        const uint2* wb = wQ + t*256 + q*8 + r;
#pragma unroll
        for (int j = 0; j < 8; ++j) {
            uint2 b = wb[j*32];
            mma16816(c[j], a, b.x, b.y);
        }
    }
}

__global__ __launch_bounds__(THREADS)
void node_mma_kernel(const float* __restrict__ x,
                     const float* __restrict__ W_in,
                     const float* __restrict__ b_in,
                     const float* __restrict__ g1,
                     const float* __restrict__ be1,
                     const float* __restrict__ W1,
                     const float* __restrict__ b1,
                     const float* __restrict__ W2,
                     const float* __restrict__ b2,
                     const float* __restrict__ g2,
                     const float* __restrict__ be2,
                     const float* __restrict__ W_out,
                     const float* __restrict__ b_out,
                     const int* __restrict__ nsp,
                     float* __restrict__ out)
{
    extern __shared__ float sm[];
    uint2* waQ = reinterpret_cast<uint2*>(sm + OFF_WA);
    uint2* wbQ = reinterpret_cast<uint2*>(sm + OFF_WB);
    uint32_t* b1h = reinterpret_cast<uint32_t*>(sm + PAR_B1H);

    const int tid  = threadIdx.x;
    const int lane = tid & 31;
    const int wid  = tid >> 5;
    const int q    = lane & 3;
    const int r    = lane >> 2;
    const int R0   = wid * 16;
    const long long row0 = (long long)blockIdx.x * ROWSB;

    // ---- stage params ----
    for (int i = tid; i < 64; i += THREADS) {
        sm[PAR_BIN+i]=b_in[i]; sm[PAR_G1+i]=g1[i]; sm[PAR_BE1+i]=be1[i];
        sm[PAR_B2+i]=b2[i];
        sm[PAR_G2+i]=g2[i];    sm[PAR_BE2+i]=be2[i];
    }
    if (tid < 32) b1h[tid] = packh2(b1[2*tid], b1[2*tid+1]);
    if (tid < 10) sm[PAR_BOUT+tid] = b_out[tid];
    for (int i = tid; i < 640; i += THREADS) sm[PAR_WOUT+i] = W_out[i];

    // ---- GEMM1: h_pre = x @ W_in, single-term fp16, double-buffered chunks ----
    float c[8][4];
#pragma unroll
    for (int j = 0; j < 8; ++j) { c[j][0]=0.f; c[j][1]=0.f; c[j][2]=0.f; c[j][3]=0.f; }

    for (int ck = 0; ck < 13; ++ck) {
        const int kbase = ck * 64;
        const int kt    = (ck < 12) ? 4 : 1;
        uint32_t* xb = reinterpret_cast<uint32_t*>(sm + ((ck & 1) ? OFF_XS1 : OFF_XS0));
        uint2*  wbuf = (ck & 1) ? wbQ : waQ;
        // stage x chunk as packed fp16 (row stride 36 words -> bank-free frag loads)
        for (int f = tid; f < ROWSB * 16; f += THREADS) {
            int row = f >> 4, c4 = f & 15;
            int gc = kbase + c4 * 4;
            float4 v = (gc < 784)
                ? *reinterpret_cast<const float4*>(x + (row0+row)*784 + gc)
                : make_float4(0.f,0.f,0.f,0.f);
            xb[row*36 + c4*2]     = packh2(v.x, v.y);
            xb[row*36 + c4*2 + 1] = packh2(v.z, v.w);
        }
        // stage W_in chunk fragments (fp16, guarded)
        const int np = kt * 256;
        for (int p = tid; p < np; p += THREADS) {
            int rr=p&7, qq=(p>>3)&3, jj=(p>>5)&7, tt=(p>>8)&3;
            int n  = 8*jj + rr;
            int ka = kbase + 16*tt + 2*qq;
            float w0 = (ka   < 784) ? W_in[ka*64+n]     : 0.f;
            float w1 = (ka+1 < 784) ? W_in[(ka+1)*64+n] : 0.f;
            float w2 = (ka+8 < 784) ? W_in[(ka+8)*64+n] : 0.f;
            float w3 = (ka+9 < 784) ? W_in[(ka+9)*64+n] : 0.f;
            wbuf[p] = make_uint2(packh2(w0, w1), packh2(w2, w3));
        }
        __syncthreads();
        for (int t = 0; t < kt; ++t) {
            const uint32_t* ra = xb + (R0 + r)*36 + 8*t;
            const uint32_t* rb = ra + 8*36;
            uint32_t a[4];
            a[0] = ra[q]; a[1] = rb[q]; a[2] = ra[q+4]; a[3] = rb[q+4];
            const uint2* wb = wbuf + t*256 + q*8 + r;
#pragma unroll
            for (int j = 0; j < 8; ++j) {
                uint2 b = wb[j*32];
                mma16816(c[j], a, b.x, b.y);
            }
        }
    }

    // ---- bias + GroupNorm1 + tanh -> h (fp32) and av (packed fp16 frags) ----
    float h[8][4];
    uint32_t av[16];
#pragma unroll
    for (int j = 0; j < 8; ++j) {
        float2 bb = *reinterpret_cast<const float2*>(sm + PAR_BIN + 8*j + 2*q);
        h[j][0] = c[j][0] + bb.x; h[j][1] = c[j][1] + bb.y;
        h[j][2] = c[j][2] + bb.x; h[j][3] = c[j][3] + bb.y;
    }
#pragma unroll
    for (int j = 0; j < 8; ++j) {
        float s1 = h[j][0] + h[j][1], s2 = h[j][0]*h[j][0] + h[j][1]*h[j][1];
        float t1 = h[j][2] + h[j][3], t2 = h[j][2]*h[j][2] + h[j][3]*h[j][3];
        s1 += __shfl_xor_sync(~0u, s1, 1); s1 += __shfl_xor_sync(~0u, s1, 2);
        s2 += __shfl_xor_sync(~0u, s2, 1); s2 += __shfl_xor_sync(~0u, s2, 2);
        t1 += __shfl_xor_sync(~0u, t1, 1); t1 += __shfl_xor_sync(~0u, t1, 2);
        t2 += __shfl_xor_sync(~0u, t2, 1); t2 += __shfl_xor_sync(~0u, t2, 2);
        float muA = s1*0.125f, vA = fmaxf(s2*0.125f - muA*muA, 0.f);
        float muB = t1*0.125f, vB = fmaxf(t2*0.125f - muB*muB, 0.f);
        float rsA = rsqrtf(vA + 1e-5f), rsB = rsqrtf(vB + 1e-5f);
        float2 gg = *reinterpret_cast<const float2*>(sm + PAR_G1  + 8*j + 2*q);
        float2 be = *reinterpret_cast<const float2*>(sm + PAR_BE1 + 8*j + 2*q);
        h[j][0] = tanhfast((h[j][0]-muA)*rsA*gg.x + be.x);
        h[j][1] = tanhfast((h[j][1]-muA)*rsA*gg.y + be.y);
        h[j][2] = tanhfast((h[j][2]-muB)*rsB*gg.x + be.x);
        h[j][3] = tanhfast((h[j][3]-muB)*rsB*gg.y + be.y);
        av[2*j]   = packh2(h[j][0], h[j][1]);
        av[2*j+1] = packh2(h[j][2], h[j][3]);
    }

    // ---- stage W1/W2 fragments (fp16) ----
    __syncthreads();
    for (int p = tid; p < 1024; p += THREADS) {
        int rr=p&7, qq=(p>>3)&3, jj=(p>>5)&7, tt=(p>>8)&3;
        int n  = 8*jj + rr;
        int ka = 16*tt + 2*qq;
        waQ[p] = make_uint2(packh2(W1[ka*64+n],     W1[(ka+1)*64+n]),
                            packh2(W1[(ka+8)*64+n], W1[(ka+9)*64+n]));
        wbQ[p] = make_uint2(packh2(W2[ka*64+n],     W2[(ka+1)*64+n]),
                            packh2(W2[(ka+8)*64+n], W2[(ka+9)*64+n]));
    }
    __syncthreads();

    // ---- RK4 (warps fully independent) ----
    const int nsteps = *nsp;
    const float dt  = 1.f / (float)nsteps;
    const float dt2 = 0.5f*dt, dt3 = dt/3.f, dt6 = dt/6.f;

    float hacc[8][4];
#pragma unroll
    for (int j = 0; j < 8; ++j)
#pragma unroll
        for (int e = 0; e < 4; ++e) hacc[j][e] = 0.f;

    const int nit = 4 * nsteps;
    for (int it = 0; it < nit; ++it) {
        int s = it & 3;
        gemm64(av, waQ, c, q, r);            // U = A @ W1
        // u = tanh(U + b1), packed fp16 -> direct A fragments for K-gemm
#pragma unroll
        for (int j = 0; j < 8; ++j) {
            uint32_t bh = b1h[4*j + q];
            av[2*j]   = tanh2(hadd2(packh2(c[j][0], c[j][1]), bh));
            av[2*j+1] = tanh2(hadd2(packh2(c[j][2], c[j][3]), bh));
        }
        gemm64(av, wbQ, c, q, r);            // K = u @ W2
        float ca = (s==0 || s==3) ? dt6 : dt3;
        float cb = (s==2) ? dt : dt2;
#pragma unroll
        for (int j = 0; j < 8; ++j) {
            float2 bb = *reinterpret_cast<const float2*>(sm + PAR_B2 + 8*j + 2*q);
            float t0, t1, t2, t3;
#pragma unroll
            for (int e = 0; e < 4; ++e) {
                float k  = c[j][e] + ((e&1) ? bb.y : bb.x);
                float hb = (s==0) ? h[j][e] : hacc[j][e];
                hb += ca * k;
                hacc[j][e] = hb;
                float tv;
                if (s == 3) { h[j][e] = hb; tv = hb; }
                else        { tv = h[j][e] + cb * k; }
                if (e==0) t0=tv; else if (e==1) t1=tv; else if (e==2) t2=tv; else t3=tv;
            }
            av[2*j]   = packh2(t0, t1);
            av[2*j+1] = packh2(t2, t3);
        }
    }

    // ---- GroupNorm2 ----
    float gn[8][4];
#pragma unroll
    for (int j = 0; j < 8; ++j) {
        float s1 = h[j][0] + h[j][1], s2 = h[j][0]*h[j][0] + h[j][1]*h[j][1];
        float t1 = h[j][2] + h[j][3], t2 = h[j][2]*h[j][2] + h[j][3]*h[j][3];
        s1 += __shfl_xor_sync(~0u, s1, 1); s1 += __shfl_xor_sync(~0u, s1, 2);
        s2 += __shfl_xor_sync(~0u, s2, 1); s2 += __shfl_xor_sync(~0u, s2, 2);
        t1 += __shfl_xor_sync(~0u, t1, 1); t1 += __shfl_xor_sync(~0u, t1, 2);
        t2 += __shfl_xor_sync(~0u, t2, 1); t2 += __shfl_xor_sync(~0u, t2, 2);
        float muA = s1*0.125f, vA = fmaxf(s2*0.125f - muA*muA, 0.f);
        float muB = t1*0.125f, vB = fmaxf(t2*0.125f - muB*muB, 0.f);
        float rsA = rsqrtf(vA + 1e-5f), rsB = rsqrtf(vB + 1e-5f);
        float2 gg = *reinterpret_cast<const float2*>(sm + PAR_G2  + 8*j + 2*q);
        float2 be = *reinterpret_cast<const float2*>(sm + PAR_BE2 + 8*j + 2*q);
        gn[j][0] = (h[j][0]-muA)*rsA*gg.x + be.x;
        gn[j][1] = (h[j][1]-muA)*rsA*gg.y + be.y;
        gn[j][2] = (h[j][2]-muB)*rsB*gg.x + be.x;
        gn[j][3] = (h[j][3]-muB)*rsB*gg.y + be.y;
    }

    // ---- logits + log_softmax ----
    float lgA[10], lgB[10];
#pragma unroll
    for (int m = 0; m < 10; ++m) { lgA[m]=0.f; lgB[m]=0.f; }
#pragma unroll
    for (int j = 0; j < 8; ++j) {
        const float* w0 = sm + PAR_WOUT + (8*j + 2*q) * 10;
        const float* w1 = w0 + 10;
#pragma unroll
        for (int m = 0; m < 10; ++m) {
            lgA[m] += gn[j][0]*w0[m] + gn[j][1]*w1[m];
            lgB[m] += gn[j][2]*w0[m] + gn[j][3]*w1[m];
        }
    }
#pragma unroll
    for (int m = 0; m < 10; ++m) {
        lgA[m] += __shfl_xor_sync(~0u, lgA[m], 1); lgA[m] += __shfl_xor_sync(~0u, lgA[m], 2);
        lgB[m] += __shfl_xor_sync(~0u, lgB[m], 1); lgB[m] += __shfl_xor_sync(~0u, lgB[m], 2);
        lgA[m] += sm[PAR_BOUT+m];
        lgB[m] += sm[PAR_BOUT+m];
    }
    if (q == 0) {
        float mxA = lgA[0], mxB = lgB[0];
#pragma unroll
        for (int m = 1; m < 10; ++m) { mxA = fmaxf(mxA, lgA[m]); mxB = fmaxf(mxB, lgB[m]); }
        float seA = 0.f, seB = 0.f;
#pragma unroll
        for (int m = 0; m < 10; ++m) { seA += expf(lgA[m]-mxA); seB += expf(lgB[m]-mxB); }
        float lseA = mxA + logf(seA), lseB = mxB + logf(seB);
        float* oa = out + (row0 + R0 + r) * 10;
        float* ob = out + (row0 + R0 + r + 8) * 10;
#pragma unroll
        for (int m = 0; m < 10; ++m) { oa[m] = lgA[m] - lseA; ob[m] = lgB[m] - lseB; }
    }
}

extern "C" void kernel_launch(void* const* d_in, const int* in_sizes, int n_in,
                              void* d_out, int out_size) {
    const float* x     = (const float*)d_in[0];
    const float* W_in  = (const float*)d_in[1];
    const float* b_in  = (const float*)d_in[2];
    const float* g1    = (const float*)d_in[3];
    const float* be1   = (const float*)d_in[4];
    const float* W1    = (const float*)d_in[5];
    const float* b1    = (const float*)d_in[6];
    const float* W2    = (const float*)d_in[7];
    const float* b2    = (const float*)d_in[8];
    const float* g2    = (const float*)d_in[9];
    const float* be2   = (const float*)d_in[10];
    const float* W_out = (const float*)d_in[11];
    const float* b_out = (const float*)d_in[12];
    const int*   nsp   = (const int*)d_in[13];
    float* out = (float*)d_out;

    const int B = in_sizes[0] / 784;
    const int nblk = B / ROWSB;
    const size_t smem = SMEM_FLOATS * sizeof(float);

    cudaFuncSetAttribute(node_mma_kernel,
                         cudaFuncAttributeMaxDynamicSharedMemorySize, (int)smem);
    node_mma_kernel<<<nblk, THREADS, smem>>>(
        x, W_in, b_in, g1, be1, W1, b1, W2, b2, g2, be2, W_out, b_out, nsp, out);
}

// round 13
// speedup vs baseline: 1.0974x; 1.0974x over previous
#include <cuda_runtime.h>
#include <cuda_fp16.h>
#include <stdint.h>

#define THREADS 256
#define ROWSB   128

// ---- shared memory float offsets ----
#define PAR_BIN  0
#define PAR_G1   64
#define PAR_BE1  128
#define PAR_B1   192
#define PAR_B2   256
#define PAR_G2   320
#define PAR_BE2  384
#define PAR_BOUT 448
#define PAR_WOUT 464                     // 640 floats -> ends 1104
#define OFF_XS   1120                    // x stage: 128 rows * 72 floats
#define OFF_WA   (OFF_XS + 128*72)       // W_in-chunk / W1 frags: 1024 uint2
#define OFF_WB   (OFF_WA + 2048)         // W2 frags: 1024 uint2
#define SMEM_FLOATS (OFF_WB + 2048)      // 14400 floats = 57600 B

__device__ __forceinline__ uint32_t packh2(float v0, float v1) {
    __half2 t = __floats2half2_rn(v0, v1);
    return *reinterpret_cast<uint32_t*>(&t);
}
__device__ __forceinline__ void mma16816(float* c, const uint32_t* a, uint32_t b0, uint32_t b1) {
    asm("mma.sync.aligned.m16n8k16.row.col.f32.f16.f16.f32 "
        "{%0,%1,%2,%3}, {%4,%5,%6,%7}, {%8,%9}, {%0,%1,%2,%3};\n"
        : "+f"(c[0]), "+f"(c[1]), "+f"(c[2]), "+f"(c[3])
        : "r"(a[0]), "r"(a[1]), "r"(a[2]), "r"(a[3]), "r"(b0), "r"(b1));
}
// packed fp16x2 tanh (hardware approx; abs err ~2^-11, same as fp16 rounding)
__device__ __forceinline__ uint32_t tanh2(uint32_t x) {
    uint32_t r; asm("tanh.approx.f16x2 %0, %1;" : "=r"(r) : "r"(x)); return r;
}
// accurate tanh for GroupNorm1 output (feeds fp32 h state)
__device__ __forceinline__ float tanhfast(float x) {
    float e;
    asm("ex2.approx.f32 %0, %1;" : "=f"(e) : "f"(x * 2.8853900817779268f));
    float d = e + 1.0f, i;
    asm("rcp.approx.f32 %0, %1;" : "=f"(i) : "f"(d));
    return fmaf(-2.0f, i, 1.0f);
}

// ODE-loop GEMM: C[16x64/warp] = A @ W, fp16; A pre-packed as av[16]
// av[2j]   = {v[j][0], v[j][1]}  (row r,   cols 2q,2q+1 of n-tile j)
// av[2j+1] = {v[j][2], v[j][3]}  (row r+8)
__device__ __forceinline__ void gemm64(const uint32_t av[16],
                                       const uint2* __restrict__ wQ,
                                       float c[8][4], int q, int r) {
#pragma unroll
    for (int j = 0; j < 8; ++j) { c[j][0]=0.f; c[j][1]=0.f; c[j][2]=0.f; c[j][3]=0.f; }
#pragma unroll
    for (int t = 0; t < 4; ++t) {
        const uint32_t* a = av + 4*t;
        const uint2* wb = wQ + t*256 + q*8 + r;
#pragma unroll
        for (int j = 0; j < 8; ++j) {
            uint2 b = wb[j*32];
            mma16816(c[j], a, b.x, b.y);
        }
    }
}

__global__ __launch_bounds__(THREADS)
void node_mma_kernel(const float* __restrict__ x,
                     const float* __restrict__ W_in,
                     const float* __restrict__ b_in,
                     const float* __restrict__ g1,
                     const float* __restrict__ be1,
                     const float* __restrict__ W1,
                     const float* __restrict__ b1,
                     const float* __restrict__ W2,
                     const float* __restrict__ b2,
                     const float* __restrict__ g2,
                     const float* __restrict__ be2,
                     const float* __restrict__ W_out,
                     const float* __restrict__ b_out,
                     const int* __restrict__ nsp,
                     float* __restrict__ out)
{
    extern __shared__ float sm[];
    uint2* waQ = reinterpret_cast<uint2*>(sm + OFF_WA);
    uint2* wbQ = reinterpret_cast<uint2*>(sm + OFF_WB);
    float* xs = sm + OFF_XS;

    const int tid  = threadIdx.x;
    const int lane = tid & 31;
    const int wid  = tid >> 5;
    const int q    = lane & 3;
    const int r    = lane >> 2;
    const int R0   = wid * 16;
    const long long row0 = (long long)blockIdx.x * ROWSB;

    // ---- stage params ----
    for (int i = tid; i < 64; i += THREADS) {
        sm[PAR_BIN+i]=b_in[i]; sm[PAR_G1+i]=g1[i]; sm[PAR_BE1+i]=be1[i];
        sm[PAR_B1+i]=b1[i];    sm[PAR_B2+i]=b2[i];
        sm[PAR_G2+i]=g2[i];    sm[PAR_BE2+i]=be2[i];
    }
    if (tid < 10) sm[PAR_BOUT+tid] = b_out[tid];
    for (int i = tid; i < 640; i += THREADS) sm[PAR_WOUT+i] = W_out[i];

    // ---- GEMM1: h_pre = x @ W_in, k chunked (12x64 + 1x16), single-term fp16 ----
    float c[8][4];
#pragma unroll
    for (int j = 0; j < 8; ++j) { c[j][0]=0.f; c[j][1]=0.f; c[j][2]=0.f; c[j][3]=0.f; }

    for (int ck = 0; ck < 13; ++ck) {
        const int kbase = ck * 64;
        const int kcur  = (ck < 12) ? 64 : 16;
        const int kt    = kcur >> 4;
        __syncthreads();
        // stage x chunk (fp32, row stride 72)
        const int nf4 = ROWSB * (kcur >> 2);
        for (int f = tid; f < nf4; f += THREADS) {
            int row = f / (kcur >> 2);
            int c4  = f % (kcur >> 2);
            float4 v = *reinterpret_cast<const float4*>(x + (row0+row)*784 + kbase + c4*4);
            float* d = xs + row*72 + c4*4;
            d[0]=v.x; d[1]=v.y; d[2]=v.z; d[3]=v.w;
        }
        // build W_in chunk B-fragments (fp16, packed uint2)
        const int np = kt * 256;
        for (int p = tid; p < np; p += THREADS) {
            int rr=p&7, qq=(p>>3)&3, jj=(p>>5)&7, tt=(p>>8)&3;
            int n  = 8*jj + rr;
            int ka = kbase + 16*tt + 2*qq;
            waQ[p] = make_uint2(packh2(W_in[ka*64+n],     W_in[(ka+1)*64+n]),
                                packh2(W_in[(ka+8)*64+n], W_in[(ka+9)*64+n]));
        }
        __syncthreads();
        for (int t = 0; t < kt; ++t) {
            const float* ra = xs + (R0 + r)*72 + 16*t + 2*q;
            const float* rb = ra + 8*72;
            float2 v00 = *reinterpret_cast<const float2*>(ra);
            float2 v01 = *reinterpret_cast<const float2*>(ra + 8);
            float2 v10 = *reinterpret_cast<const float2*>(rb);
            float2 v11 = *reinterpret_cast<const float2*>(rb + 8);
            uint32_t a[4];
            a[0] = packh2(v00.x, v00.y);
            a[1] = packh2(v10.x, v10.y);
            a[2] = packh2(v01.x, v01.y);
            a[3] = packh2(v11.x, v11.y);
            const uint2* wb = waQ + t*256 + q*8 + r;
#pragma unroll
            for (int j = 0; j < 8; ++j) {
                uint2 b = wb[j*32];
                mma16816(c[j], a, b.x, b.y);
            }
        }
    }

    // ---- bias + GroupNorm1 + tanh -> h (fp32) and av (packed fp16 frags) ----
    float h[8][4];
    uint32_t av[16];
#pragma unroll
    for (int j = 0; j < 8; ++j) {
        float2 bb = *reinterpret_cast<const float2*>(sm + PAR_BIN + 8*j + 2*q);
        h[j][0] = c[j][0] + bb.x; h[j][1] = c[j][1] + bb.y;
        h[j][2] = c[j][2] + bb.x; h[j][3] = c[j][3] + bb.y;
    }
#pragma unroll
    for (int j = 0; j < 8; ++j) {
        float s1 = h[j][0] + h[j][1], s2 = h[j][0]*h[j][0] + h[j][1]*h[j][1];
        float t1 = h[j][2] + h[j][3], t2 = h[j][2]*h[j][2] + h[j][3]*h[j][3];
        s1 += __shfl_xor_sync(~0u, s1, 1); s1 += __shfl_xor_sync(~0u, s1, 2);
        s2 += __shfl_xor_sync(~0u, s2, 1); s2 += __shfl_xor_sync(~0u, s2, 2);
        t1 += __shfl_xor_sync(~0u, t1, 1); t1 += __shfl_xor_sync(~0u, t1, 2);
        t2 += __shfl_xor_sync(~0u, t2, 1); t2 += __shfl_xor_sync(~0u, t2, 2);
        float muA = s1*0.125f, vA = fmaxf(s2*0.125f - muA*muA, 0.f);
        float muB = t1*0.125f, vB = fmaxf(t2*0.125f - muB*muB, 0.f);
        float rsA = rsqrtf(vA + 1e-5f), rsB = rsqrtf(vB + 1e-5f);
        float2 gg = *reinterpret_cast<const float2*>(sm + PAR_G1  + 8*j + 2*q);
        float2 be = *reinterpret_cast<const float2*>(sm + PAR_BE1 + 8*j + 2*q);
        h[j][0] = tanhfast((h[j][0]-muA)*rsA*gg.x + be.x);
        h[j][1] = tanhfast((h[j][1]-muA)*rsA*gg.y + be.y);
        h[j][2] = tanhfast((h[j][2]-muB)*rsB*gg.x + be.x);
        h[j][3] = tanhfast((h[j][3]-muB)*rsB*gg.y + be.y);
        av[2*j]   = packh2(h[j][0], h[j][1]);
        av[2*j+1] = packh2(h[j][2], h[j][3]);
    }

    // ---- stage W1/W2 fragments (fp16) ----
    __syncthreads();
    for (int p = tid; p < 1024; p += THREADS) {
        int rr=p&7, qq=(p>>3)&3, jj=(p>>5)&7, tt=(p>>8)&3;
        int n  = 8*jj + rr;
        int ka = 16*tt + 2*qq;
        waQ[p] = make_uint2(packh2(W1[ka*64+n],     W1[(ka+1)*64+n]),
                            packh2(W1[(ka+8)*64+n], W1[(ka+9)*64+n]));
        wbQ[p] = make_uint2(packh2(W2[ka*64+n],     W2[(ka+1)*64+n]),
                            packh2(W2[(ka+8)*64+n], W2[(ka+9)*64+n]));
    }
    __syncthreads();

    // ---- RK4 (warps fully independent) ----
    const int nsteps = *nsp;
    const float dt  = 1.f / (float)nsteps;
    const float dt2 = 0.5f*dt, dt3 = dt/3.f, dt6 = dt/6.f;

    float hacc[8][4];
#pragma unroll
    for (int j = 0; j < 8; ++j)
#pragma unroll
        for (int e = 0; e < 4; ++e) hacc[j][e] = 0.f;

    const int nit = 4 * nsteps;
    for (int it = 0; it < nit; ++it) {
        int s = it & 3;
        gemm64(av, waQ, c, q, r);            // U = A @ W1
        // u = tanh(U + b1), packed fp16 -> direct A fragments for K-gemm
#pragma unroll
        for (int j = 0; j < 8; ++j) {
            float2 bb = *reinterpret_cast<const float2*>(sm + PAR_B1 + 8*j + 2*q);
            av[2*j]   = tanh2(packh2(c[j][0] + bb.x, c[j][1] + bb.y));
            av[2*j+1] = tanh2(packh2(c[j][2] + bb.x, c[j][3] + bb.y));
        }
        gemm64(av, wbQ, c, q, r);            // K = u @ W2
        float ca = (s==0 || s==3) ? dt6 : dt3;
        float cb = (s==2) ? dt : dt2;
#pragma unroll
        for (int j = 0; j < 8; ++j) {
            float2 bb = *reinterpret_cast<const float2*>(sm + PAR_B2 + 8*j + 2*q);
            float t0, t1, t2, t3;
#pragma unroll
            for (int e = 0; e < 4; ++e) {
                float k  = c[j][e] + ((e&1) ? bb.y : bb.x);
                float hb = (s==0) ? h[j][e] : hacc[j][e];
                hb += ca * k;
                hacc[j][e] = hb;
                float tv;
                if (s == 3) { h[j][e] = hb; tv = hb; }
                else        { tv = h[j][e] + cb * k; }
                if (e==0) t0=tv; else if (e==1) t1=tv; else if (e==2) t2=tv; else t3=tv;
            }
            av[2*j]   = packh2(t0, t1);
            av[2*j+1] = packh2(t2, t3);
        }
    }

    // ---- GroupNorm2 ----
    float gn[8][4];
#pragma unroll
    for (int j = 0; j < 8; ++j) {
        float s1 = h[j][0] + h[j][1], s2 = h[j][0]*h[j][0] + h[j][1]*h[j][1];
        float t1 = h[j][2] + h[j][3], t2 = h[j][2]*h[j][2] + h[j][3]*h[j][3];
        s1 += __shfl_xor_sync(~0u, s1, 1); s1 += __shfl_xor_sync(~0u, s1, 2);
        s2 += __shfl_xor_sync(~0u, s2, 1); s2 += __shfl_xor_sync(~0u, s2, 2);
        t1 += __shfl_xor_sync(~0u, t1, 1); t1 += __shfl_xor_sync(~0u, t1, 2);
        t2 += __shfl_xor_sync(~0u, t2, 1); t2 += __shfl_xor_sync(~0u, t2, 2);
        float muA = s1*0.125f, vA = fmaxf(s2*0.125f - muA*muA, 0.f);
        float muB = t1*0.125f, vB = fmaxf(t2*0.125f - muB*muB, 0.f);
        float rsA = rsqrtf(vA + 1e-5f), rsB = rsqrtf(vB + 1e-5f);
        float2 gg = *reinterpret_cast<const float2*>(sm + PAR_G2  + 8*j + 2*q);
        float2 be = *reinterpret_cast<const float2*>(sm + PAR_BE2 + 8*j + 2*q);
        gn[j][0] = (h[j][0]-muA)*rsA*gg.x + be.x;
        gn[j][1] = (h[j][1]-muA)*rsA*gg.y + be.y;
        gn[j][2] = (h[j][2]-muB)*rsB*gg.x + be.x;
        gn[j][3] = (h[j][3]-muB)*rsB*gg.y + be.y;
    }

    // ---- logits + log_softmax ----
    float lgA[10], lgB[10];
#pragma unroll
    for (int m = 0; m < 10; ++m) { lgA[m]=0.f; lgB[m]=0.f; }
#pragma unroll
    for (int j = 0; j < 8; ++j) {
        const float* w0 = sm + PAR_WOUT + (8*j + 2*q) * 10;
        const float* w1 = w0 + 10;
#pragma unroll
        for (int m = 0; m < 10; ++m) {
            lgA[m] += gn[j][0]*w0[m] + gn[j][1]*w1[m];
            lgB[m] += gn[j][2]*w0[m] + gn[j][3]*w1[m];
        }
    }
#pragma unroll
    for (int m = 0; m < 10; ++m) {
        lgA[m] += __shfl_xor_sync(~0u, lgA[m], 1); lgA[m] += __shfl_xor_sync(~0u, lgA[m], 2);
        lgB[m] += __shfl_xor_sync(~0u, lgB[m], 1); lgB[m] += __shfl_xor_sync(~0u, lgB[m], 2);
        lgA[m] += sm[PAR_BOUT+m];
        lgB[m] += sm[PAR_BOUT+m];
    }
    if (q == 0) {
        float mxA = lgA[0], mxB = lgB[0];
#pragma unroll
        for (int m = 1; m < 10; ++m) { mxA = fmaxf(mxA, lgA[m]); mxB = fmaxf(mxB, lgB[m]); }
        float seA = 0.f, seB = 0.f;
#pragma unroll
        for (int m = 0; m < 10; ++m) { seA += expf(lgA[m]-mxA); seB += expf(lgB[m]-mxB); }
        float lseA = mxA + logf(seA), lseB = mxB + logf(seB);
        float* oa = out + (row0 + R0 + r) * 10;
        float* ob = out + (row0 + R0 + r + 8) * 10;
#pragma unroll
        for (int m = 0; m < 10; ++m) { oa[m] = lgA[m] - lseA; ob[m] = lgB[m] - lseB; }
    }
}

extern "C" void kernel_launch(void* const* d_in, const int* in_sizes, int n_in,
                              void* d_out, int out_size) {
    const float* x     = (const float*)d_in[0];
    const float* W_in  = (const float*)d_in[1];
    const float* b_in  = (const float*)d_in[2];
    const float* g1    = (const float*)d_in[3];
    const float* be1   = (const float*)d_in[4];
    const float* W1    = (const float*)d_in[5];
    const float* b1    = (const float*)d_in[6];
    const float* W2    = (const float*)d_in[7];
    const float* b2    = (const float*)d_in[8];
    const float* g2    = (const float*)d_in[9];
    const float* be2   = (const float*)d_in[10];
    const float* W_out = (const float*)d_in[11];
    const float* b_out = (const float*)d_in[12];
    const int*   nsp   = (const int*)d_in[13];
    float* out = (float*)d_out;

    const int B = in_sizes[0] / 784;
    const int nblk = B / ROWSB;
    const size_t smem = SMEM_FLOATS * sizeof(float);

    cudaFuncSetAttribute(node_mma_kernel,
                         cudaFuncAttributeMaxDynamicSharedMemorySize, (int)smem);
    node_mma_kernel<<<nblk, THREADS, smem>>>(
        x, W_in, b_in, g1, be1, W1, b1, W2, b2, g2, be2, W_out, b_out, nsp, out);
}